// round 11
// baseline (speedup 1.0000x reference)
#include <cuda_runtime.h>
#include <cuda_bf16.h>
#include <cstdint>

// LengthRegulator. Live work (predictor is dead code in the reference):
//   cum = cumsum(target_durations, axis=1)
//   padded[b,f,:] = (f < cum[b,-1]) ? x[b, upper_bound(cum[b], f), :] : 0
//   durations_out = target_durations
// B=8, T=1024, D=1024, F=8192. Output fp32: [B*F*D padded][B*T durations].
//
// R11: fused scan+expand (R10) with the coherence bug fixed: g_tok consumer
// loads use ld.global.cg (L2, coherent) instead of __ldg (.nc, non-coherent,
// which returned stale data intra-kernel). Expand path identical to R9.

#define LR_B 8
#define LR_T 1024
#define LR_D 1024
#define LR_F 8192
#define LR_V4 (LR_D / 4)          // 256 float4 per row
#define FRAMES 8                  // frames per expand block (uniform)
#define SLABS (LR_F / FRAMES)     // 1024 slabs per batch
#define NTHR 256

__device__ int g_tok[LR_B * LR_F];                     // frame -> token (-1 invalid)
__device__ __align__(128) unsigned g_flag[LR_B * 32];  // 128B-padded per-batch flags

__device__ __forceinline__ void flag_release(unsigned* p) {
    asm volatile("st.release.gpu.u32 [%0], %1;" :: "l"(p), "r"(1u) : "memory");
}
__device__ __forceinline__ void flag_acquire_spin(const unsigned* p) {
    unsigned v;
    do {
        asm volatile("ld.acquire.gpu.u32 %0, [%1];" : "=r"(v) : "l"(p) : "memory");
        if (v == 0) __nanosleep(32);
    } while (v == 0);
}

// ---------------------------------------------------------------------------
// Fused kernel. bid < LR_B: scan role. else: expand role.
// ---------------------------------------------------------------------------
__global__ void __launch_bounds__(NTHR)
lr_fused_kernel(const float* __restrict__ x,
                const int* __restrict__ dur,
                float* __restrict__ out,
                float* __restrict__ dur_out) {
    const int bid = blockIdx.x;
    const int tid = threadIdx.x;

    if (bid < LR_B) {
        // ================= scan role: batch = bid =================
        const int b = bid;
        __shared__ int warp_sums[8];
        __shared__ int s_total;

        // 4 consecutive durations per thread (aligned int4)
        const int4 dv = __ldg(reinterpret_cast<const int4*>(dur + b * LR_T) + tid);
        const int s0 = dv.x;
        const int s1 = s0 + dv.y;
        const int s2 = s1 + dv.z;
        const int s3 = s2 + dv.w;

        // block inclusive scan of per-thread sums (8 warps)
        const int lane = tid & 31, wid = tid >> 5;
        int s = s3;
        #pragma unroll
        for (int o = 1; o < 32; o <<= 1) {
            int u = __shfl_up_sync(0xFFFFFFFFu, s, o);
            if (lane >= o) s += u;
        }
        if (lane == 31) warp_sums[wid] = s;
        __syncthreads();
        if (wid == 0 && lane < 8) {
            int ws = warp_sums[lane];
            #pragma unroll
            for (int o = 1; o < 8; o <<= 1) {
                int u = __shfl_up_sync(0xFFu, ws, o);
                if (lane >= o) ws += u;
            }
            warp_sums[lane] = ws;
        }
        __syncthreads();
        const int base = ((wid > 0) ? warp_sums[wid - 1] : 0) + s - s3; // exclusive
        if (tid == NTHR - 1) s_total = base + s3;
        __syncthreads();
        const int total = s_total;

        // durations pass-through (float4 convert)
        if (dur_out) {
            float4 fo = make_float4((float)dv.x, (float)dv.y,
                                    (float)dv.z, (float)dv.w);
            reinterpret_cast<float4*>(dur_out + b * LR_T)[tid] = fo;
        }

        // invalid frames
        int* tokb = &g_tok[b * LR_F];
        for (int f = total + tid; f < LR_F; f += NTHR) tokb[f] = -1;

        // scatter: token 4*tid+k owns [base+s_{k-1}, base+s_k)
        const int t0 = tid * 4;
        int st = base;
        #pragma unroll
        for (int k = 0; k < 4; ++k) {
            const int en = base + ((k == 0) ? s0 : (k == 1) ? s1 : (k == 2) ? s2 : s3);
            for (int f = st; f < en; ++f) tokb[f] = t0 + k;
            st = en;
        }

        __syncthreads();
        __threadfence();
        if (tid == 0) flag_release(&g_flag[b * 32]);

    } else {
        // ================= expand role =================
        const int e  = bid - LR_B;
        const int b  = e >> 10;             // SLABS = 1024 per batch
        const int f0 = (e & (SLABS - 1)) * FRAMES;
        const int i  = tid;                 // 0..255

        if (tid == 0) flag_acquire_spin(&g_flag[b * 32]);
        __syncthreads();

        // COHERENT token loads (ld.global.cg -> L2). NOT __ldg/.nc: that path
        // is non-coherent and returned stale data intra-kernel (R10 bug).
        const int* tokp = &g_tok[b * LR_F + f0];
        int tok[FRAMES];
        #pragma unroll
        for (int j = 0; j < FRAMES; ++j) tok[j] = __ldcg(&tokp[j]);

        const float4* x4 = reinterpret_cast<const float4*>(x) +
                           (size_t)b * LR_T * LR_V4 + i;
        float4* o = reinterpret_cast<float4*>(out) +
                    ((size_t)b * LR_F + f0) * LR_V4 + i;

        const float4 z = make_float4(0.f, 0.f, 0.f, 0.f);

        bool lead[FRAMES];
        lead[0] = true;
        #pragma unroll
        for (int j = 1; j < FRAMES; ++j) lead[j] = (tok[j] != tok[j - 1]);

        // Independent predicated row loads (x is pre-launch data: __ldg OK)
        float4 v[FRAMES];
        #pragma unroll
        for (int j = 0; j < FRAMES; ++j) {
            v[j] = z;
            if (lead[j] && tok[j] >= 0) v[j] = __ldg(&x4[(size_t)tok[j] * LR_V4]);
        }
        #pragma unroll
        for (int j = 1; j < FRAMES; ++j) {
            if (!lead[j]) v[j] = v[j - 1];
        }
        #pragma unroll
        for (int j = 0; j < FRAMES; ++j) {
            __stcs(&o[(size_t)j * LR_V4], v[j]);
        }
    }
}

extern "C" void kernel_launch(void* const* d_in, const int* in_sizes, int n_in,
                              void* d_out, int out_size) {
    const float* x   = (const float*)d_in[0];  // [B, T, D] fp32
    const int*   dur = (const int*)  d_in[1];  // [B, T] int32
    float* out = (float*)d_out;

    const long long padded_elems = (long long)LR_B * LR_F * LR_D;
    float* dur_out =
        ((long long)out_size >= padded_elems + (long long)LR_B * LR_T)
            ? out + padded_elems : nullptr;

    // reset per-batch flags (memset node in the graph; no allocation)
    void* flag_ptr = nullptr;
    cudaGetSymbolAddress(&flag_ptr, g_flag);
    cudaMemsetAsync(flag_ptr, 0, sizeof(unsigned) * LR_B * 32);

    lr_fused_kernel<<<LR_B + LR_B * SLABS, NTHR>>>(x, dur, out, dur_out);
}

// round 12
// speedup vs baseline: 1.0437x; 1.0437x over previous
#include <cuda_runtime.h>
#include <cuda_bf16.h>
#include <cstdint>

// LengthRegulator. Live work (predictor is dead code in the reference):
//   cum = cumsum(target_durations, axis=1)
//   padded[b,f,:] = (f < cum[b,-1]) ? x[b, upper_bound(cum[b], f), :] : 0
//   durations_out = target_durations
// B=8, T=1024, D=1024, F=8192. Output fp32: [B*F*D padded][B*T durations].
//
// R12: revert to the R9 two-kernel structure (best expand: 44.1us, DRAM 68%),
// hide the scan kernel + launch gap with Programmatic Dependent Launch:
// scan triggers completion at entry, expand launches with
// programmaticStreamSerializationAllowed and gridDepSync's before reading
// g_tok. Scan upgraded to 8x256 int4 form (from R11's validated scan role).

#define LR_B 8
#define LR_T 1024
#define LR_D 1024
#define LR_F 8192
#define LR_V4 (LR_D / 4)          // 256 float4 per row
#define FRAMES 8                  // frames per expand block (uniform)
#define SLABS (LR_F / FRAMES)     // 1024 slabs per batch
#define NTHR 256

__device__ int g_tok[LR_B * LR_F];   // frame -> token (-1 = invalid)

// ---------------------------------------------------------------------------
// Kernel 1: per-batch scan + frame->token scatter + durations pass-through.
// 8 blocks x 256 threads, 4 tokens/thread via int4.
// ---------------------------------------------------------------------------
__global__ void __launch_bounds__(NTHR)
lr_scan_kernel(const int* __restrict__ dur, float* __restrict__ dur_out) {
#if __CUDA_ARCH__ >= 900
    cudaTriggerProgrammaticLaunchCompletion();  // let expand grid schedule now
#endif
    const int b   = blockIdx.x;
    const int tid = threadIdx.x;
    __shared__ int warp_sums[8];
    __shared__ int s_total;

    const int4 dv = __ldg(reinterpret_cast<const int4*>(dur + b * LR_T) + tid);
    const int s0 = dv.x;
    const int s1 = s0 + dv.y;
    const int s2 = s1 + dv.z;
    const int s3 = s2 + dv.w;

    const int lane = tid & 31, wid = tid >> 5;
    int s = s3;
    #pragma unroll
    for (int o = 1; o < 32; o <<= 1) {
        int u = __shfl_up_sync(0xFFFFFFFFu, s, o);
        if (lane >= o) s += u;
    }
    if (lane == 31) warp_sums[wid] = s;
    __syncthreads();
    if (wid == 0 && lane < 8) {
        int ws = warp_sums[lane];
        #pragma unroll
        for (int o = 1; o < 8; o <<= 1) {
            int u = __shfl_up_sync(0xFFu, ws, o);
            if (lane >= o) ws += u;
        }
        warp_sums[lane] = ws;
    }
    __syncthreads();
    const int base = ((wid > 0) ? warp_sums[wid - 1] : 0) + s - s3;  // exclusive
    if (tid == NTHR - 1) s_total = base + s3;
    __syncthreads();
    const int total = s_total;

    if (dur_out) {
        float4 fo = make_float4((float)dv.x, (float)dv.y,
                                (float)dv.z, (float)dv.w);
        reinterpret_cast<float4*>(dur_out + b * LR_T)[tid] = fo;
    }

    int* tokb = &g_tok[b * LR_F];
    for (int f = total + tid; f < LR_F; f += NTHR) tokb[f] = -1;

    const int t0 = tid * 4;
    int st = base;
    #pragma unroll
    for (int k = 0; k < 4; ++k) {
        const int en = base + ((k == 0) ? s0 : (k == 1) ? s1 : (k == 2) ? s2 : s3);
        for (int f = st; f < en; ++f) tokb[f] = t0 + k;
        st = en;
    }
}

// ---------------------------------------------------------------------------
// Kernel 2: balanced expand, independent dedup'd loads (R9, unchanged except
// the PDL grid-dependency sync before consuming g_tok).
// ---------------------------------------------------------------------------
__global__ void __launch_bounds__(LR_V4)
lr_expand_kernel(const float* __restrict__ x, float* __restrict__ out) {
#if __CUDA_ARCH__ >= 900
    cudaGridDependencySynchronize();  // wait for scan kernel's writes
#endif
    const int b  = blockIdx.y;
    const int f0 = blockIdx.x * FRAMES;
    const int i  = threadIdx.x;  // 0..255

    const int* tokp = &g_tok[b * LR_F + f0];
    int tok[FRAMES];
    #pragma unroll
    for (int j = 0; j < FRAMES; ++j) tok[j] = __ldg(&tokp[j]);

    const float4* x4 = reinterpret_cast<const float4*>(x) +
                       (size_t)b * LR_T * LR_V4 + i;
    float4* o = reinterpret_cast<float4*>(out) +
                ((size_t)b * LR_F + f0) * LR_V4 + i;

    const float4 z = make_float4(0.f, 0.f, 0.f, 0.f);

    bool lead[FRAMES];
    lead[0] = true;
    #pragma unroll
    for (int j = 1; j < FRAMES; ++j) lead[j] = (tok[j] != tok[j - 1]);

    float4 v[FRAMES];
    #pragma unroll
    for (int j = 0; j < FRAMES; ++j) {
        v[j] = z;
        if (lead[j] && tok[j] >= 0) v[j] = __ldg(&x4[(size_t)tok[j] * LR_V4]);
    }
    #pragma unroll
    for (int j = 1; j < FRAMES; ++j) {
        if (!lead[j]) v[j] = v[j - 1];
    }
    #pragma unroll
    for (int j = 0; j < FRAMES; ++j) {
        __stcs(&o[(size_t)j * LR_V4], v[j]);
    }
}

extern "C" void kernel_launch(void* const* d_in, const int* in_sizes, int n_in,
                              void* d_out, int out_size) {
    const float* x   = (const float*)d_in[0];  // [B, T, D] fp32
    const int*   dur = (const int*)  d_in[1];  // [B, T] int32
    float* out = (float*)d_out;

    const long long padded_elems = (long long)LR_B * LR_F * LR_D;
    float* dur_out =
        ((long long)out_size >= padded_elems + (long long)LR_B * LR_T)
            ? out + padded_elems : nullptr;

    lr_scan_kernel<<<LR_B, NTHR>>>(dur, dur_out);

    // Expand with Programmatic Dependent Launch: schedules while scan runs.
    cudaLaunchConfig_t cfg = {};
    cfg.gridDim  = dim3(SLABS, LR_B);
    cfg.blockDim = dim3(LR_V4);
    cfg.stream   = 0;  // legacy default stream (capture stream)
    cudaLaunchAttribute attrs[1];
    attrs[0].id = cudaLaunchAttributeProgrammaticStreamSerialization;
    attrs[0].val.programmaticStreamSerializationAllowed = 1;
    cfg.attrs    = attrs;
    cfg.numAttrs = 1;
    cudaError_t err = cudaLaunchKernelEx(&cfg, lr_expand_kernel, x, out);
    if (err != cudaSuccess) {
        // Fallback: plain launch (still correct, just serialized)
        lr_expand_kernel<<<dim3(SLABS, LR_B), LR_V4>>>(x, out);
    }
}